// round 14
// baseline (speedup 1.0000x reference)
#include <cuda_runtime.h>
#include <cstdint>

#define BSZ   256
#define SEQ   1024
#define HID   512
#define TGT   256
#define NCTA  128
#define TPB   512
#define NBP   128          // batch pairs (2 rows / thread)
#define NKH   4            // K-quarters
#define KP    (HID / 2)    // total k-pairs
#define KPQ   (KP / NKH)   // k-pairs per K-quarter (64)
#define REDW  34           // reduction slots per bp: 16 acc0 + 16 acc1 + xd0 + xd1

typedef unsigned long long ull;

// Hidden state, double buffered, layout [k_pair][batch] as packed float2 (b64).
__device__ ull g_h[2][KP * BSZ];
__device__ unsigned g_bar;

__global__ void k_init() { g_bar = 0u; }

__device__ __forceinline__ ull ffma2(ull a, ull b, ull c) {
    ull d;
    asm("fma.rn.f32x2 %0, %1, %2, %3;" : "=l"(d) : "l"(a), "l"(b), "l"(c));
    return d;
}
__device__ __forceinline__ ull fadd2(ull a, ull b) {
    ull d;
    asm("add.rn.f32x2 %0, %1, %2;" : "=l"(d) : "l"(a), "l"(b));
    return d;
}
__device__ __forceinline__ ull pack2(float x, float y) {
    float2 t = make_float2(x, y);
    return *reinterpret_cast<ull*>(&t);
}
__device__ __forceinline__ float lanesum(ull v) {
    float2 t = *reinterpret_cast<float2*>(&v);
    return t.x + t.y;
}

__device__ __forceinline__ ulonglong2 ldcg128(const ull* p) {
    ulonglong2 v;
    asm("ld.global.cg.v2.u64 {%0,%1}, [%2];" : "=l"(v.x), "=l"(v.y) : "l"(p));
    return v;
}

__device__ __forceinline__ float sigf(float x) {
    return __fdividef(1.0f, 1.0f + __expf(-x));
}
__device__ __forceinline__ float tanh_(float x) {
    return __fdividef(2.0f, 1.0f + __expf(-2.0f * x)) - 1.0f;
}

// Monotonic-counter grid barrier (128 CTAs co-resident, 1/SM)
__device__ __forceinline__ void grid_barrier(unsigned target) {
    __syncthreads();
    if (threadIdx.x == 0) {
        __threadfence();
        atomicAdd(&g_bar, 1u);
        unsigned v;
        do {
            asm volatile("ld.acquire.gpu.u32 %0, [%1];" : "=r"(v) : "l"(&g_bar));
        } while (v < target);
    }
    __syncthreads();
}

// 2 k-pairs (4 ks) x 2 rows. hA = {row0 kp, row1 kp}, hB = {row0 kp+1, row1 kp+1}.
// One LDS.128 weight load feeds 4 ffma2.
template <bool XDOT>
__device__ __forceinline__ void compute2(ulonglong2 hA, ulonglong2 hB,
                                         const float* __restrict__ ws,
                                         const float* __restrict__ ls,
                                         int kp2, ull* acc0, ull* acc1,
                                         ull& xd0, ull& xd1) {
    if (XDOT) {
        ulonglong2 lw = *reinterpret_cast<const ulonglong2*>(ls + 2 * kp2);
        xd0 = ffma2(hA.x, lw.x, xd0);
        xd0 = ffma2(hB.x, lw.y, xd0);
        xd1 = ffma2(hA.y, lw.x, xd1);
        xd1 = ffma2(hB.y, lw.y, xd1);
    }
#pragma unroll
    for (int g = 0; g < 16; g++) {
        ulonglong2 w = *reinterpret_cast<const ulonglong2*>(ws + g * HID + 2 * kp2);
        acc0[g] = ffma2(hA.x, w.x, acc0[g]);
        acc0[g] = ffma2(hB.x, w.y, acc0[g]);
        acc1[g] = ffma2(hA.y, w.x, acc1[g]);
        acc1[g] = ffma2(hB.y, w.y, acc1[g]);
    }
}

// K-quarter reduction (KPQ k-pairs). hin = &g_h[buf][(kh*KPQ)*BSZ + 2*bp];
// ws/ls pre-offset by kh*(HID/4) floats so kp2 is local [0, KPQ).
template <bool XDOT>
__device__ __forceinline__ void kloop(const ull* __restrict__ hin,
                                      const float* __restrict__ ws,
                                      const float* __restrict__ ls,
                                      ull* acc0, ull* acc1, ull& xd0, ull& xd1) {
    ulonglong2 A0 = ldcg128(hin + 0 * BSZ), A1 = ldcg128(hin + 1 * BSZ);
    ulonglong2 B0 = ldcg128(hin + 2 * BSZ), B1 = ldcg128(hin + 3 * BSZ);

#pragma unroll 1
    for (int kp2 = 0; kp2 < KPQ; kp2 += 4) {
        ulonglong2 hA = A0, hB = A1;
        if (kp2 + 4 < KPQ) {
            A0 = ldcg128(hin + (kp2 + 4) * BSZ);
            A1 = ldcg128(hin + (kp2 + 5) * BSZ);
        }
        compute2<XDOT>(hA, hB, ws, ls, kp2, acc0, acc1, xd0, xd1);

        hA = B0; hB = B1;
        if (kp2 + 4 < KPQ) {
            B0 = ldcg128(hin + (kp2 + 6) * BSZ);
            B1 = ldcg128(hin + (kp2 + 7) * BSZ);
        }
        compute2<XDOT>(hA, hB, ws, ls, kp2 + 2, acc0, acc1, xd0, xd1);
    }
}

extern __shared__ float dynsmem[];

__global__ void __launch_bounds__(TPB, 1)
seq2seq_kernel(const float* __restrict__ inp,
               const float* __restrict__ eWih, const float* __restrict__ eWhh,
               const float* __restrict__ ebih, const float* __restrict__ ebhh,
               const float* __restrict__ dWih, const float* __restrict__ dWhh,
               const float* __restrict__ dbih, const float* __restrict__ dbhh,
               const float* __restrict__ linW, const float* __restrict__ linb,
               float* __restrict__ out) {
    float* wsE = dynsmem;             // [16][HID] enc Whh slice (raw fp32)
    float* wsD = wsE + 16 * HID;      // [16][HID] dec Whh slice
    float* ls  = wsD + 16 * HID;      // [HID] lin_W
    ull*   red = reinterpret_cast<ull*>(ls + HID);  // [3][NBP][REDW] partials
    __shared__ float bsE[16], wxE[16], bsD[16], wxD[16];
    __shared__ float s_linb;

    const int tid = threadIdx.x;
    const int bp  = tid & (NBP - 1);  // batch pair: rows 2bp, 2bp+1
    const int kh  = tid >> 7;         // K-quarter: 0..3
    const int cta = blockIdx.x;
    const int c0  = cta * 4;          // first hidden column of this CTA
    const int kp0 = c0 >> 1;          // k-pair index of our output columns

    // Stage weights: gate-col g = gate*4 + ci -> row j = gate*HID + c0 + ci
    for (int idx = tid; idx < 16 * HID; idx += TPB) {
        int g = idx >> 9;
        int k = idx & (HID - 1);
        int gate = g >> 2, ci = g & 3;
        int j = gate * HID + c0 + ci;
        wsE[idx] = eWhh[j * HID + k];
        wsD[idx] = dWhh[j * HID + k];
    }
    for (int k = tid; k < HID; k += TPB) ls[k] = linW[k];
    if (tid < 16) {
        int gate = tid >> 2, ci = tid & 3;
        int j = gate * HID + c0 + ci;
        bsE[tid] = ebih[j] + ebhh[j];
        wxE[tid] = eWih[j];
        bsD[tid] = dbih[j] + dbhh[j];
        wxD[tid] = dWih[j];
    }
    if (tid == 0) s_linb = linb[0];

    // Zero this CTA's columns of h buffer 0 (kh==0 threads own rows 2bp,2bp+1)
    if (kh == 0) {
        *reinterpret_cast<ulonglong2*>(&g_h[0][(kp0 + 0) * BSZ + 2 * bp]) = make_ulonglong2(0, 0);
        *reinterpret_cast<ulonglong2*>(&g_h[0][(kp0 + 1) * BSZ + 2 * bp]) = make_ulonglong2(0, 0);
    }

    float c40[4] = {0.f, 0.f, 0.f, 0.f};   // c state row 0
    float c41[4] = {0.f, 0.f, 0.f, 0.f};   // c state row 1
    unsigned bt = 0;

    // Pre-offset views for this thread's K-quarter
    const int hoff = kh * KPQ * BSZ + 2 * bp;
    const float* wsEh = wsE + kh * (HID / NKH);
    const float* wsDh = wsD + kh * (HID / NKH);
    const float* lsh  = ls  + kh * (HID / NKH);
    ull* myred = red + ((kh - 1) * NBP + bp) * REDW;   // valid for kh>=1
    ull* rd0 = red + bp * REDW;                        // kh==1 partial
    ull* rd1 = red + (NBP + bp) * REDW;                // kh==2 partial
    ull* rd2 = red + (2 * NBP + bp) * REDW;            // kh==3 partial

    const int b0 = 2 * bp, b1 = 2 * bp + 1;

    // ---------------- encoder: 1024 steps ----------------
    for (int s = 0; s < SEQ; s++) {
        bt += NCTA;
        grid_barrier(bt);

        ull acc0[16], acc1[16];
        if (kh == 0) {
            float x0 = __ldg(inp + b0 * SEQ + s);
            float x1 = __ldg(inp + b1 * SEQ + s);
#pragma unroll
            for (int g = 0; g < 16; g++) {
                acc0[g] = pack2(fmaf(x0, wxE[g], bsE[g]), 0.f);
                acc1[g] = pack2(fmaf(x1, wxE[g], bsE[g]), 0.f);
            }
        } else {
#pragma unroll
            for (int g = 0; g < 16; g++) { acc0[g] = 0ull; acc1[g] = 0ull; }
        }

        ull xd0 = 0ull, xd1 = 0ull;
        kloop<false>(&g_h[s & 1][hoff], wsEh, lsh, acc0, acc1, xd0, xd1);

        if (kh != 0) {
#pragma unroll
            for (int g = 0; g < 16; g++) { myred[g] = acc0[g]; myred[16 + g] = acc1[g]; }
        }
        __syncthreads();

        if (kh == 0) {
#pragma unroll
            for (int g = 0; g < 16; g++) {
                acc0[g] = fadd2(fadd2(acc0[g], rd0[g]), fadd2(rd1[g], rd2[g]));
                acc1[g] = fadd2(fadd2(acc1[g], rd0[16 + g]), fadd2(rd1[16 + g], rd2[16 + g]));
            }

            ull* hout = &g_h[(s + 1) & 1][0];
            float hn0[4], hn1[4];
#pragma unroll
            for (int ci = 0; ci < 4; ci++) {
                float gi = lanesum(acc0[ci]), gf = lanesum(acc0[4 + ci]);
                float gg = lanesum(acc0[8 + ci]), go = lanesum(acc0[12 + ci]);
                float cn = sigf(gf) * c40[ci] + sigf(gi) * tanh_(gg);
                c40[ci] = cn;
                hn0[ci] = sigf(go) * tanh_(cn);

                gi = lanesum(acc1[ci]); gf = lanesum(acc1[4 + ci]);
                gg = lanesum(acc1[8 + ci]); go = lanesum(acc1[12 + ci]);
                cn = sigf(gf) * c41[ci] + sigf(gi) * tanh_(gg);
                c41[ci] = cn;
                hn1[ci] = sigf(go) * tanh_(cn);
            }
            *reinterpret_cast<ulonglong2*>(&hout[(kp0 + 0) * BSZ + b0]) =
                make_ulonglong2(pack2(hn0[0], hn0[1]), pack2(hn1[0], hn1[1]));
            *reinterpret_cast<ulonglong2*>(&hout[(kp0 + 1) * BSZ + b0]) =
                make_ulonglong2(pack2(hn0[2], hn0[3]), pack2(hn1[2], hn1[3]));
        }
    }

    // ---------------- decoder: 256 steps ----------------
    float x0 = __ldg(inp + b0 * SEQ + (SEQ - 1));
    float x1 = __ldg(inp + b1 * SEQ + (SEQ - 1));

    for (int d = 0; d < TGT; d++) {
        int s = SEQ + d;
        bt += NCTA;
        grid_barrier(bt);

        ull acc0[16], acc1[16];
        if (kh == 0) {
#pragma unroll
            for (int g = 0; g < 16; g++) {
                acc0[g] = pack2(bsD[g], 0.f);
                acc1[g] = pack2(bsD[g], 0.f);
            }
        } else {
#pragma unroll
            for (int g = 0; g < 16; g++) { acc0[g] = 0ull; acc1[g] = 0ull; }
        }

        ull xd0 = 0ull, xd1 = 0ull;
        kloop<true>(&g_h[s & 1][hoff], wsDh, lsh, acc0, acc1, xd0, xd1);

        if (kh != 0) {
#pragma unroll
            for (int g = 0; g < 16; g++) { myred[g] = acc0[g]; myred[16 + g] = acc1[g]; }
            myred[32] = xd0;
            myred[33] = xd1;
        }
        __syncthreads();

        if (kh == 0) {
#pragma unroll
            for (int g = 0; g < 16; g++) {
                acc0[g] = fadd2(fadd2(acc0[g], rd0[g]), fadd2(rd1[g], rd2[g]));
                acc1[g] = fadd2(fadd2(acc1[g], rd0[16 + g]), fadd2(rd1[16 + g], rd2[16 + g]));
            }
            xd0 = fadd2(fadd2(xd0, rd0[32]), fadd2(rd1[32], rd2[32]));
            xd1 = fadd2(fadd2(xd1, rd0[33]), fadd2(rd1[33], rd2[33]));

            if (d > 0) {
                x0 = lanesum(xd0) + s_linb;   // out_{d-1} == fed-back x_d
                x1 = lanesum(xd1) + s_linb;
                if (cta == 0) {
                    out[b0 * TGT + (d - 1)] = x0;
                    out[b1 * TGT + (d - 1)] = x1;
                }
            }
            // add x * Wih contribution (lane 0 only)
#pragma unroll
            for (int g = 0; g < 16; g++) {
                float2 u0 = *reinterpret_cast<float2*>(&acc0[g]);
                u0.x = fmaf(x0, wxD[g], u0.x);
                acc0[g] = *reinterpret_cast<ull*>(&u0);
                float2 u1 = *reinterpret_cast<float2*>(&acc1[g]);
                u1.x = fmaf(x1, wxD[g], u1.x);
                acc1[g] = *reinterpret_cast<ull*>(&u1);
            }

            ull* hout = &g_h[(s + 1) & 1][0];
            float hn0[4], hn1[4];
#pragma unroll
            for (int ci = 0; ci < 4; ci++) {
                float gi = lanesum(acc0[ci]), gf = lanesum(acc0[4 + ci]);
                float gg = lanesum(acc0[8 + ci]), go = lanesum(acc0[12 + ci]);
                float cn = sigf(gf) * c40[ci] + sigf(gi) * tanh_(gg);
                c40[ci] = cn;
                hn0[ci] = sigf(go) * tanh_(cn);

                gi = lanesum(acc1[ci]); gf = lanesum(acc1[4 + ci]);
                gg = lanesum(acc1[8 + ci]); go = lanesum(acc1[12 + ci]);
                cn = sigf(gf) * c41[ci] + sigf(gi) * tanh_(gg);
                c41[ci] = cn;
                hn1[ci] = sigf(go) * tanh_(cn);
            }
            *reinterpret_cast<ulonglong2*>(&hout[(kp0 + 0) * BSZ + b0]) =
                make_ulonglong2(pack2(hn0[0], hn0[1]), pack2(hn1[0], hn1[1]));
            *reinterpret_cast<ulonglong2*>(&hout[(kp0 + 1) * BSZ + b0]) =
                make_ulonglong2(pack2(hn0[2], hn0[3]), pack2(hn1[2], hn1[3]));
        }
    }

    // ---------------- final output (dot of last decoder h) ----------------
    bt += NCTA;
    grid_barrier(bt);
    if (cta == 0 && kh == 0) {
        const ull* hin = &g_h[(SEQ + TGT) & 1][2 * bp];
        ull xd0 = 0ull, xd1 = 0ull;
        for (int kp = 0; kp < KP; kp++) {
            ulonglong2 hv = ldcg128(hin + kp * BSZ);
            ull lw = *reinterpret_cast<const ull*>(ls + 2 * kp);
            xd0 = ffma2(hv.x, lw, xd0);
            xd1 = ffma2(hv.y, lw, xd1);
        }
        out[b0 * TGT + (TGT - 1)] = lanesum(xd0) + s_linb;
        out[b1 * TGT + (TGT - 1)] = lanesum(xd1) + s_linb;
    }
}

extern "C" void kernel_launch(void* const* d_in, const int* in_sizes, int n_in,
                              void* d_out, int out_size) {
    const float* inp  = (const float*)d_in[0];
    const float* eWih = (const float*)d_in[1];
    const float* eWhh = (const float*)d_in[2];
    const float* ebih = (const float*)d_in[3];
    const float* ebhh = (const float*)d_in[4];
    const float* dWih = (const float*)d_in[5];
    const float* dWhh = (const float*)d_in[6];
    const float* dbih = (const float*)d_in[7];
    const float* dbhh = (const float*)d_in[8];
    const float* linW = (const float*)d_in[9];
    const float* linb = (const float*)d_in[10];
    float* out = (float*)d_out;

    // 66 KB weights + 104 KB reduction buffer
    size_t smem = (size_t)(2 * 16 * HID + HID) * sizeof(float)
                + (size_t)3 * NBP * REDW * sizeof(ull);
    cudaFuncSetAttribute((const void*)seq2seq_kernel,
                         cudaFuncAttributeMaxDynamicSharedMemorySize, (int)smem);

    k_init<<<1, 1>>>();
    seq2seq_kernel<<<NCTA, TPB, smem>>>(inp, eWih, eWhh, ebih, ebhh,
                                        dWih, dWhh, dbih, dbhh, linW, linb, out);
}

// round 15
// speedup vs baseline: 1.7329x; 1.7329x over previous
#include <cuda_runtime.h>
#include <cstdint>

#define BSZ   256
#define SEQ   1024
#define HID   512
#define TGT   256
#define NCTA  128
#define TPB   256
#define NBP   128          // batch pairs (2 rows / thread)
#define KP    (HID / 2)    // total k-pairs
#define KP2   (KP / 2)     // k-pairs per K-half (128)
#define REDW  34           // reduction slots per bp: 16 acc0 + 16 acc1 + xd0 + xd1

typedef unsigned long long ull;

// Hidden state, double buffered, layout [k_pair][batch] as packed float2 (b64).
__device__ ull g_h[2][KP * BSZ];
__device__ unsigned g_bar;

__global__ void k_init() { g_bar = 0u; }

__device__ __forceinline__ ull ffma2(ull a, ull b, ull c) {
    ull d;
    asm("fma.rn.f32x2 %0, %1, %2, %3;" : "=l"(d) : "l"(a), "l"(b), "l"(c));
    return d;
}
__device__ __forceinline__ ull fadd2(ull a, ull b) {
    ull d;
    asm("add.rn.f32x2 %0, %1, %2;" : "=l"(d) : "l"(a), "l"(b));
    return d;
}
__device__ __forceinline__ ull pack2(float x, float y) {
    float2 t = make_float2(x, y);
    return *reinterpret_cast<ull*>(&t);
}
__device__ __forceinline__ float lanesum(ull v) {
    float2 t = *reinterpret_cast<float2*>(&v);
    return t.x + t.y;
}

__device__ __forceinline__ ulonglong2 ldcg128(const ull* p) {
    ulonglong2 v;
    asm("ld.global.cg.v2.u64 {%0,%1}, [%2];" : "=l"(v.x), "=l"(v.y) : "l"(p));
    return v;
}

__device__ __forceinline__ float sigf(float x) {
    return __fdividef(1.0f, 1.0f + __expf(-x));
}
__device__ __forceinline__ float tanh_(float x) {
    return __fdividef(2.0f, 1.0f + __expf(-2.0f * x)) - 1.0f;
}

// Monotonic-counter grid barrier (128 CTAs co-resident, 1/SM)
__device__ __forceinline__ void grid_barrier(unsigned target) {
    __syncthreads();
    if (threadIdx.x == 0) {
        __threadfence();
        atomicAdd(&g_bar, 1u);
        unsigned v;
        do {
            asm volatile("ld.acquire.gpu.u32 %0, [%1];" : "=r"(v) : "l"(&g_bar));
        } while (v < target);
    }
    __syncthreads();
}

// 2 k-pairs (4 ks) x 2 rows. hA = {row0 kp, row1 kp}, hB = {row0 kp+1, row1 kp+1}.
// One LDS.128 weight load feeds 4 ffma2.
template <bool XDOT>
__device__ __forceinline__ void compute2(ulonglong2 hA, ulonglong2 hB,
                                         const float* __restrict__ ws,
                                         const float* __restrict__ ls,
                                         int kp2, ull* acc0, ull* acc1,
                                         ull& xd0, ull& xd1) {
    if (XDOT) {
        ulonglong2 lw = *reinterpret_cast<const ulonglong2*>(ls + 2 * kp2);
        xd0 = ffma2(hA.x, lw.x, xd0);
        xd0 = ffma2(hB.x, lw.y, xd0);
        xd1 = ffma2(hA.y, lw.x, xd1);
        xd1 = ffma2(hB.y, lw.y, xd1);
    }
#pragma unroll
    for (int g = 0; g < 16; g++) {
        ulonglong2 w = *reinterpret_cast<const ulonglong2*>(ws + g * HID + 2 * kp2);
        acc0[g] = ffma2(hA.x, w.x, acc0[g]);
        acc0[g] = ffma2(hB.x, w.y, acc0[g]);
        acc1[g] = ffma2(hA.y, w.x, acc1[g]);
        acc1[g] = ffma2(hB.y, w.y, acc1[g]);
    }
}

// K-half reduction (KP2 k-pairs). hin = &g_h[buf][(kh*KP2)*BSZ + 2*bp];
// ws/ls pre-offset by kh*(HID/2) floats so kp2 is local [0, KP2).
template <bool XDOT>
__device__ __forceinline__ void kloop(const ull* __restrict__ hin,
                                      const float* __restrict__ ws,
                                      const float* __restrict__ ls,
                                      ull* acc0, ull* acc1, ull& xd0, ull& xd1) {
    ulonglong2 A0 = ldcg128(hin + 0 * BSZ), A1 = ldcg128(hin + 1 * BSZ);
    ulonglong2 B0 = ldcg128(hin + 2 * BSZ), B1 = ldcg128(hin + 3 * BSZ);

#pragma unroll 1
    for (int kp2 = 0; kp2 < KP2; kp2 += 4) {
        ulonglong2 hA = A0, hB = A1;
        if (kp2 + 4 < KP2) {
            A0 = ldcg128(hin + (kp2 + 4) * BSZ);
            A1 = ldcg128(hin + (kp2 + 5) * BSZ);
        }
        compute2<XDOT>(hA, hB, ws, ls, kp2, acc0, acc1, xd0, xd1);

        hA = B0; hB = B1;
        if (kp2 + 4 < KP2) {
            B0 = ldcg128(hin + (kp2 + 6) * BSZ);
            B1 = ldcg128(hin + (kp2 + 7) * BSZ);
        }
        compute2<XDOT>(hA, hB, ws, ls, kp2 + 2, acc0, acc1, xd0, xd1);
    }
}

extern __shared__ float dynsmem[];

__global__ void __launch_bounds__(TPB, 1)
seq2seq_kernel(const float* __restrict__ inp,
               const float* __restrict__ eWih, const float* __restrict__ eWhh,
               const float* __restrict__ ebih, const float* __restrict__ ebhh,
               const float* __restrict__ dWih, const float* __restrict__ dWhh,
               const float* __restrict__ dbih, const float* __restrict__ dbhh,
               const float* __restrict__ linW, const float* __restrict__ linb,
               float* __restrict__ out) {
    float* wsE = dynsmem;             // [16][HID] enc Whh slice (raw fp32)
    float* wsD = wsE + 16 * HID;      // [16][HID] dec Whh slice
    float* ls  = wsD + 16 * HID;      // [HID] lin_W
    ull*   red = reinterpret_cast<ull*>(ls + HID);  // [NBP][REDW] kh=1 partials
    __shared__ float bsE[16], wxE[16], bsD[16], wxD[16];
    __shared__ float s_linb;

    const int tid = threadIdx.x;
    const int bp  = tid & (NBP - 1);  // batch pair: rows 2bp, 2bp+1
    const int kh  = tid >> 7;         // K-half: 0 or 1
    const int cta = blockIdx.x;
    const int c0  = cta * 4;          // first hidden column of this CTA
    const int kp0 = c0 >> 1;          // k-pair index of our output columns

    // Stage weights: gate-col g = gate*4 + ci -> row j = gate*HID + c0 + ci
    for (int idx = tid; idx < 16 * HID; idx += TPB) {
        int g = idx >> 9;
        int k = idx & (HID - 1);
        int gate = g >> 2, ci = g & 3;
        int j = gate * HID + c0 + ci;
        wsE[idx] = eWhh[j * HID + k];
        wsD[idx] = dWhh[j * HID + k];
    }
    for (int k = tid; k < HID; k += TPB) ls[k] = linW[k];
    if (tid < 16) {
        int gate = tid >> 2, ci = tid & 3;
        int j = gate * HID + c0 + ci;
        bsE[tid] = ebih[j] + ebhh[j];
        wxE[tid] = eWih[j];
        bsD[tid] = dbih[j] + dbhh[j];
        wxD[tid] = dWih[j];
    }
    if (tid == 0) s_linb = linb[0];

    // Zero this CTA's columns of h buffer 0 (kh==0 threads own rows 2bp,2bp+1)
    if (kh == 0) {
        *reinterpret_cast<ulonglong2*>(&g_h[0][(kp0 + 0) * BSZ + 2 * bp]) = make_ulonglong2(0, 0);
        *reinterpret_cast<ulonglong2*>(&g_h[0][(kp0 + 1) * BSZ + 2 * bp]) = make_ulonglong2(0, 0);
    }

    float c40[4] = {0.f, 0.f, 0.f, 0.f};   // c state row 0 (kh==0 only)
    float c41[4] = {0.f, 0.f, 0.f, 0.f};   // c state row 1
    unsigned bt = 0;

    // Pre-offset views for this thread's K-half
    const int hoff = kh * KP2 * BSZ + 2 * bp;
    const float* wsEh = wsE + kh * (HID / 2);
    const float* wsDh = wsD + kh * (HID / 2);
    const float* lsh  = ls  + kh * (HID / 2);
    ull* rd = red + bp * REDW;        // kh=1 writes, kh=0 reads

    const int b0 = 2 * bp, b1 = 2 * bp + 1;

    // ---------------- encoder: 1024 steps ----------------
    for (int s = 0; s < SEQ; s++) {
        bt += NCTA;
        grid_barrier(bt);

        ull acc0[16], acc1[16];
        if (kh == 0) {
            float x0 = __ldg(inp + b0 * SEQ + s);
            float x1 = __ldg(inp + b1 * SEQ + s);
#pragma unroll
            for (int g = 0; g < 16; g++) {
                acc0[g] = pack2(fmaf(x0, wxE[g], bsE[g]), 0.f);
                acc1[g] = pack2(fmaf(x1, wxE[g], bsE[g]), 0.f);
            }
        } else {
#pragma unroll
            for (int g = 0; g < 16; g++) { acc0[g] = 0ull; acc1[g] = 0ull; }
        }

        ull xd0 = 0ull, xd1 = 0ull;
        kloop<false>(&g_h[s & 1][hoff], wsEh, lsh, acc0, acc1, xd0, xd1);

        if (kh == 1) {
#pragma unroll
            for (int g = 0; g < 16; g++) { rd[g] = acc0[g]; rd[16 + g] = acc1[g]; }
        }
        __syncthreads();

        if (kh == 0) {
#pragma unroll
            for (int g = 0; g < 16; g++) {
                acc0[g] = fadd2(acc0[g], rd[g]);
                acc1[g] = fadd2(acc1[g], rd[16 + g]);
            }

            ull* hout = &g_h[(s + 1) & 1][0];
            float hn0[4], hn1[4];
#pragma unroll
            for (int ci = 0; ci < 4; ci++) {
                float gi = lanesum(acc0[ci]), gf = lanesum(acc0[4 + ci]);
                float gg = lanesum(acc0[8 + ci]), go = lanesum(acc0[12 + ci]);
                float cn = sigf(gf) * c40[ci] + sigf(gi) * tanh_(gg);
                c40[ci] = cn;
                hn0[ci] = sigf(go) * tanh_(cn);

                gi = lanesum(acc1[ci]); gf = lanesum(acc1[4 + ci]);
                gg = lanesum(acc1[8 + ci]); go = lanesum(acc1[12 + ci]);
                cn = sigf(gf) * c41[ci] + sigf(gi) * tanh_(gg);
                c41[ci] = cn;
                hn1[ci] = sigf(go) * tanh_(cn);
            }
            *reinterpret_cast<ulonglong2*>(&hout[(kp0 + 0) * BSZ + b0]) =
                make_ulonglong2(pack2(hn0[0], hn0[1]), pack2(hn1[0], hn1[1]));
            *reinterpret_cast<ulonglong2*>(&hout[(kp0 + 1) * BSZ + b0]) =
                make_ulonglong2(pack2(hn0[2], hn0[3]), pack2(hn1[2], hn1[3]));
        }
    }

    // ---------------- decoder: 256 steps ----------------
    float x0 = __ldg(inp + b0 * SEQ + (SEQ - 1));
    float x1 = __ldg(inp + b1 * SEQ + (SEQ - 1));

    for (int d = 0; d < TGT; d++) {
        int s = SEQ + d;
        bt += NCTA;
        grid_barrier(bt);

        ull acc0[16], acc1[16];
        if (kh == 0) {
#pragma unroll
            for (int g = 0; g < 16; g++) {
                acc0[g] = pack2(bsD[g], 0.f);
                acc1[g] = pack2(bsD[g], 0.f);
            }
        } else {
#pragma unroll
            for (int g = 0; g < 16; g++) { acc0[g] = 0ull; acc1[g] = 0ull; }
        }

        ull xd0 = 0ull, xd1 = 0ull;
        kloop<true>(&g_h[s & 1][hoff], wsDh, lsh, acc0, acc1, xd0, xd1);

        if (kh == 1) {
#pragma unroll
            for (int g = 0; g < 16; g++) { rd[g] = acc0[g]; rd[16 + g] = acc1[g]; }
            rd[32] = xd0;
            rd[33] = xd1;
        }
        __syncthreads();

        if (kh == 0) {
#pragma unroll
            for (int g = 0; g < 16; g++) {
                acc0[g] = fadd2(acc0[g], rd[g]);
                acc1[g] = fadd2(acc1[g], rd[16 + g]);
            }
            xd0 = fadd2(xd0, rd[32]);
            xd1 = fadd2(xd1, rd[33]);

            if (d > 0) {
                x0 = lanesum(xd0) + s_linb;   // out_{d-1} == fed-back x_d
                x1 = lanesum(xd1) + s_linb;
                if (cta == 0) {
                    out[b0 * TGT + (d - 1)] = x0;
                    out[b1 * TGT + (d - 1)] = x1;
                }
            }
            // add x * Wih contribution (lane 0 only)
#pragma unroll
            for (int g = 0; g < 16; g++) {
                float2 u0 = *reinterpret_cast<float2*>(&acc0[g]);
                u0.x = fmaf(x0, wxD[g], u0.x);
                acc0[g] = *reinterpret_cast<ull*>(&u0);
                float2 u1 = *reinterpret_cast<float2*>(&acc1[g]);
                u1.x = fmaf(x1, wxD[g], u1.x);
                acc1[g] = *reinterpret_cast<ull*>(&u1);
            }

            ull* hout = &g_h[(s + 1) & 1][0];
            float hn0[4], hn1[4];
#pragma unroll
            for (int ci = 0; ci < 4; ci++) {
                float gi = lanesum(acc0[ci]), gf = lanesum(acc0[4 + ci]);
                float gg = lanesum(acc0[8 + ci]), go = lanesum(acc0[12 + ci]);
                float cn = sigf(gf) * c40[ci] + sigf(gi) * tanh_(gg);
                c40[ci] = cn;
                hn0[ci] = sigf(go) * tanh_(cn);

                gi = lanesum(acc1[ci]); gf = lanesum(acc1[4 + ci]);
                gg = lanesum(acc1[8 + ci]); go = lanesum(acc1[12 + ci]);
                cn = sigf(gf) * c41[ci] + sigf(gi) * tanh_(gg);
                c41[ci] = cn;
                hn1[ci] = sigf(go) * tanh_(cn);
            }
            *reinterpret_cast<ulonglong2*>(&hout[(kp0 + 0) * BSZ + b0]) =
                make_ulonglong2(pack2(hn0[0], hn0[1]), pack2(hn1[0], hn1[1]));
            *reinterpret_cast<ulonglong2*>(&hout[(kp0 + 1) * BSZ + b0]) =
                make_ulonglong2(pack2(hn0[2], hn0[3]), pack2(hn1[2], hn1[3]));
        }
    }

    // ---------------- final output (dot of last decoder h) ----------------
    bt += NCTA;
    grid_barrier(bt);
    if (cta == 0 && kh == 0) {
        const ull* hin = &g_h[(SEQ + TGT) & 1][2 * bp];
        ull xd0 = 0ull, xd1 = 0ull;
        for (int kp = 0; kp < KP; kp++) {
            ulonglong2 hv = ldcg128(hin + kp * BSZ);
            ull lw = *reinterpret_cast<const ull*>(ls + 2 * kp);
            xd0 = ffma2(hv.x, lw, xd0);
            xd1 = ffma2(hv.y, lw, xd1);
        }
        out[b0 * TGT + (TGT - 1)] = lanesum(xd0) + s_linb;
        out[b1 * TGT + (TGT - 1)] = lanesum(xd1) + s_linb;
    }
}

extern "C" void kernel_launch(void* const* d_in, const int* in_sizes, int n_in,
                              void* d_out, int out_size) {
    const float* inp  = (const float*)d_in[0];
    const float* eWih = (const float*)d_in[1];
    const float* eWhh = (const float*)d_in[2];
    const float* ebih = (const float*)d_in[3];
    const float* ebhh = (const float*)d_in[4];
    const float* dWih = (const float*)d_in[5];
    const float* dWhh = (const float*)d_in[6];
    const float* dbih = (const float*)d_in[7];
    const float* dbhh = (const float*)d_in[8];
    const float* linW = (const float*)d_in[9];
    const float* linb = (const float*)d_in[10];
    float* out = (float*)d_out;

    // 66 KB weights + 34 KB reduction buffer
    size_t smem = (size_t)(2 * 16 * HID + HID) * sizeof(float)
                + (size_t)NBP * REDW * sizeof(ull);
    cudaFuncSetAttribute((const void*)seq2seq_kernel,
                         cudaFuncAttributeMaxDynamicSharedMemorySize, (int)smem);

    k_init<<<1, 1>>>();
    seq2seq_kernel<<<NCTA, TPB, smem>>>(inp, eWih, eWhh, ebih, ebhh,
                                        dWih, dWhh, dbih, dbhh, linW, linb, out);
}